// round 1
// baseline (speedup 1.0000x reference)
#include <cuda_runtime.h>
#include <math.h>

#define N_NODES 30000
#define N_EDGES 60000
#define FEAT    256
#define HID     1024
#define OUT_DIM 256
#define RANK    64

// ---------------- scratch (static device globals; no runtime allocation) ----
__device__ float g_emb_new [(size_t)N_NODES * RANK];     //  7.7 MB
__device__ float g_hid     [(size_t)N_NODES * HID];      //  123 MB
__device__ float g_emb_new2[(size_t)N_NODES * OUT_DIM];  // 30.7 MB
__device__ float g_acc     [(size_t)N_NODES * OUT_DIM];  // 30.7 MB

// ---------------- generic tiled SGEMM:  C = act(A @ W[:K] + wrow + bias) ----
// A: M x K row-major, W: (K(+1)) x N row-major. wrow == optional extra row of
// W (the "ones column" contribution), may be nullptr.
#define TM 64
#define TN 64
#define TK 16
#define SST 72   // smem row stride (floats): keeps float4 rows 16B-aligned

__global__ __launch_bounds__(256) void gemm_kernel(
    const float* __restrict__ A, const float* __restrict__ W,
    const float* __restrict__ bias, const float* __restrict__ wrow,
    float* __restrict__ C, int M, int N, int K, int do_relu)
{
    __shared__ float As[TK][SST];
    __shared__ float Bs[TK][SST];
    const int tid = threadIdx.x;
    const int tx  = tid & 15;
    const int ty  = tid >> 4;
    const int m0  = blockIdx.y * TM;
    const int n0  = blockIdx.x * TN;

    const int arow = tid >> 2;          // 0..63
    const int acol = (tid & 3) << 2;    // 0,4,8,12
    const int brow = tid >> 4;          // 0..15
    const int bcol = (tid & 15) << 2;   // 0..60

    float acc[4][4] = {{0.f,0.f,0.f,0.f},{0.f,0.f,0.f,0.f},
                       {0.f,0.f,0.f,0.f},{0.f,0.f,0.f,0.f}};

    for (int k0 = 0; k0 < K; k0 += TK) {
        float4 av = make_float4(0.f, 0.f, 0.f, 0.f);
        if (m0 + arow < M)
            av = *(const float4*)(A + (size_t)(m0 + arow) * K + k0 + acol);
        As[acol + 0][arow] = av.x;
        As[acol + 1][arow] = av.y;
        As[acol + 2][arow] = av.z;
        As[acol + 3][arow] = av.w;
        *(float4*)&Bs[brow][bcol] =
            *(const float4*)(W + (size_t)(k0 + brow) * N + n0 + bcol);
        __syncthreads();
#pragma unroll
        for (int k = 0; k < TK; k++) {
            float4 a = *(const float4*)&As[k][ty << 2];
            float4 b = *(const float4*)&Bs[k][tx << 2];
            acc[0][0] = fmaf(a.x, b.x, acc[0][0]);
            acc[0][1] = fmaf(a.x, b.y, acc[0][1]);
            acc[0][2] = fmaf(a.x, b.z, acc[0][2]);
            acc[0][3] = fmaf(a.x, b.w, acc[0][3]);
            acc[1][0] = fmaf(a.y, b.x, acc[1][0]);
            acc[1][1] = fmaf(a.y, b.y, acc[1][1]);
            acc[1][2] = fmaf(a.y, b.z, acc[1][2]);
            acc[1][3] = fmaf(a.y, b.w, acc[1][3]);
            acc[2][0] = fmaf(a.z, b.x, acc[2][0]);
            acc[2][1] = fmaf(a.z, b.y, acc[2][1]);
            acc[2][2] = fmaf(a.z, b.z, acc[2][2]);
            acc[2][3] = fmaf(a.z, b.w, acc[2][3]);
            acc[3][0] = fmaf(a.w, b.x, acc[3][0]);
            acc[3][1] = fmaf(a.w, b.y, acc[3][1]);
            acc[3][2] = fmaf(a.w, b.z, acc[3][2]);
            acc[3][3] = fmaf(a.w, b.w, acc[3][3]);
        }
        __syncthreads();
    }

    float bn[4];
#pragma unroll
    for (int j = 0; j < 4; j++) {
        int n = n0 + (tx << 2) + j;
        bn[j] = bias[n] + (wrow ? wrow[n] : 0.f);
    }
#pragma unroll
    for (int i = 0; i < 4; i++) {
        int m = m0 + (ty << 2) + i;
        if (m < M) {
            float4 v;
            v.x = acc[i][0] + bn[0];
            v.y = acc[i][1] + bn[1];
            v.z = acc[i][2] + bn[2];
            v.w = acc[i][3] + bn[3];
            if (do_relu) {
                v.x = fmaxf(v.x, 0.f); v.y = fmaxf(v.y, 0.f);
                v.z = fmaxf(v.z, 0.f); v.w = fmaxf(v.w, 0.f);
            }
            *(float4*)(C + (size_t)m * N + n0 + (tx << 2)) = v;
        }
    }
}

// ---------------- edge kernel -----------------------------------------------
// Per edge e (size in {2,3,4}; mask[s] == (s < size)):
//   scale_s = deg[node_s]^a, a = size<=3 ? 1/3 : 1/4
//   t_s = scale_s * emb_new[node_s]   (invalid slots == 1)
//   loo_s = prod_{r != s} t_r
//   gf = global_emb^(4-size) * inv_fact(size)     (GLOBAL_DEGREE == 1)
//   h_s = tanh(loo_s * gf)
//   contrib_s = h_s @ qW + qb + relu(sum_s emb_new2[node_s])
//   atomicAdd into acc[node_s]
// One output column per thread; qW column held in 64 registers per thread.
__global__ __launch_bounds__(256) void edge_kernel(
    const float* __restrict__ emb_new,
    const float* __restrict__ emb_new2,
    const int*   __restrict__ edge_nodes,
    const int*   __restrict__ edge_size,
    const int*   __restrict__ node_degree,
    const float* __restrict__ global_emb,
    const float* __restrict__ qW,
    const float* __restrict__ qb,
    float*       __restrict__ accum)
{
    __shared__ float h_s[4][RANK];
    __shared__ float sge[RANK];
    __shared__ float sscale[4];
    const int tid = threadIdx.x;

    float qw[RANK];
#pragma unroll
    for (int j = 0; j < RANK; j++) qw[j] = qW[j * OUT_DIM + tid];
    const float qbc = qb[tid];
    if (tid < RANK) sge[tid] = global_emb[tid];
    __syncthreads();

    for (int e = blockIdx.x; e < N_EDGES; e += gridDim.x) {
        const int4 nd = ((const int4*)edge_nodes)[e];
        const int na0 = nd.x, na1 = nd.y, na2 = nd.z, na3 = nd.w;
        const int sz = edge_size[e];

        if (tid < 4) {
            int node = (tid == 0) ? na0 : (tid == 1) ? na1 : (tid == 2) ? na2 : na3;
            float sc = 1.f;
            if (tid < sz) {
                float d = (float)node_degree[node];
                sc = (sz <= 3) ? cbrtf(d) : sqrtf(sqrtf(d));
            }
            sscale[tid] = sc;
        }

        // esum2 (column tid), independent of smem written this iteration
        float r2 = emb_new2[(size_t)na0 * OUT_DIM + tid]
                 + emb_new2[(size_t)na1 * OUT_DIM + tid];
        if (sz > 2) r2 += emb_new2[(size_t)na2 * OUT_DIM + tid];
        if (sz > 3) r2 += emb_new2[(size_t)na3 * OUT_DIM + tid];
        r2 = fmaxf(r2, 0.f);

        __syncthreads();   // sscale ready

        if (tid < RANK) {
            const int j = tid;
            const int kk = 4 - sz;
            const float ge = sge[j];
            const float invf = (sz == 2) ? 1.f : (sz == 3) ? 0.5f : (1.f / 6.f);
            const float gf = invf * (kk == 0 ? 1.f : (kk == 1 ? ge : ge * ge));
            float t0 = sscale[0] * emb_new[(size_t)na0 * RANK + j];
            float t1 = sscale[1] * emb_new[(size_t)na1 * RANK + j];
            float t2 = (sz > 2) ? sscale[2] * emb_new[(size_t)na2 * RANK + j] : 1.f;
            float t3 = (sz > 3) ? sscale[3] * emb_new[(size_t)na3 * RANK + j] : 1.f;
            float t01 = t0 * t1, t23 = t2 * t3;
            h_s[0][j] = tanhf(t1 * t23 * gf);
            h_s[1][j] = tanhf(t0 * t23 * gf);
            if (sz > 2) h_s[2][j] = tanhf(t01 * t3 * gf);
            if (sz > 3) h_s[3][j] = tanhf(t01 * t2 * gf);
        }
        __syncthreads();   // h_s ready

        auto slot = [&](const float* hrow, int node) {
            const float4* h4 = (const float4*)hrow;
            float a = qbc;
#pragma unroll
            for (int jj = 0; jj < 16; jj++) {
                float4 hv = h4[jj];
                a = fmaf(hv.x, qw[4 * jj + 0], a);
                a = fmaf(hv.y, qw[4 * jj + 1], a);
                a = fmaf(hv.z, qw[4 * jj + 2], a);
                a = fmaf(hv.w, qw[4 * jj + 3], a);
            }
            atomicAdd(&accum[(size_t)node * OUT_DIM + tid], a + r2);
        };
        slot(h_s[0], na0);
        slot(h_s[1], na1);
        if (sz > 2) slot(h_s[2], na2);
        if (sz > 3) slot(h_s[3], na3);

        __syncthreads();   // protect smem reuse next edge
    }
}

// ---------------- helpers ----------------------------------------------------
__global__ void zero_kernel(float* __restrict__ p, int n)
{
    int i = blockIdx.x * blockDim.x + threadIdx.x;
    if (i < n) p[i] = 0.f;
}

__global__ void finalize_kernel(const float* __restrict__ accum,
                                const int*   __restrict__ node_degree,
                                float*       __restrict__ out)
{
    int idx = blockIdx.x * blockDim.x + threadIdx.x;
    if (idx < N_NODES * OUT_DIM) {
        int node = idx >> 8;   // OUT_DIM == 256
        float v = accum[idx] / (float)node_degree[node];
        out[idx] += fmaxf(v, 0.f);   // out already holds the relu residual
    }
}

// ---------------- launch -----------------------------------------------------
extern "C" void kernel_launch(void* const* d_in, const int* in_sizes, int n_in,
                              void* d_out, int out_size)
{
    (void)in_sizes; (void)n_in; (void)out_size;
    const float* embedding  = (const float*)d_in[0];
    const float* global_emb = (const float*)d_in[1];
    const float* pW   = (const float*)d_in[2];
    const float* pb   = (const float*)d_in[3];
    const float* qW   = (const float*)d_in[4];
    const float* qb   = (const float*)d_in[5];
    const float* p2W1 = (const float*)d_in[6];
    const float* p2b1 = (const float*)d_in[7];
    const float* p2W2 = (const float*)d_in[8];
    const float* p2b2 = (const float*)d_in[9];
    const float* aW   = (const float*)d_in[10];
    const float* ab   = (const float*)d_in[11];
    const int* edge_nodes  = (const int*)d_in[12];
    // d_in[13] = edge_mask (bool) — unused: mask[s] == (s < edge_size)
    const int* edge_size   = (const int*)d_in[14];
    const int* node_degree = (const int*)d_in[15];
    float* out = (float*)d_out;

    float *emb_new, *hid, *emb_new2, *acc;
    cudaGetSymbolAddress((void**)&emb_new,  g_emb_new);
    cudaGetSymbolAddress((void**)&hid,      g_hid);
    cudaGetSymbolAddress((void**)&emb_new2, g_emb_new2);
    cudaGetSymbolAddress((void**)&acc,      g_acc);

    dim3 blk(256);
    const int mby = (N_NODES + TM - 1) / TM;  // 469

    // emb_new = embedding @ pW[:256] + pW[256] + pb
    gemm_kernel<<<dim3(RANK / TN, mby), blk>>>(
        embedding, pW, pb, pW + (size_t)FEAT * RANK,
        emb_new, N_NODES, RANK, FEAT, 0);
    // hid = relu(embedding @ p2W1[:256] + p2W1[256] + p2b1)
    gemm_kernel<<<dim3(HID / TN, mby), blk>>>(
        embedding, p2W1, p2b1, p2W1 + (size_t)FEAT * HID,
        hid, N_NODES, HID, FEAT, 1);
    // emb_new2 = hid @ p2W2 + p2b2
    gemm_kernel<<<dim3(OUT_DIM / TN, mby), blk>>>(
        hid, p2W2, p2b2, nullptr,
        emb_new2, N_NODES, OUT_DIM, HID, 0);
    // residual = relu(embedding @ aW[:256] + aW[256] + ab) -> d_out
    gemm_kernel<<<dim3(OUT_DIM / TN, mby), blk>>>(
        embedding, aW, ab, aW + (size_t)FEAT * OUT_DIM,
        out, N_NODES, OUT_DIM, FEAT, 1);

    zero_kernel<<<(N_NODES * OUT_DIM + 255) / 256, blk>>>(acc, N_NODES * OUT_DIM);

    edge_kernel<<<1480, blk>>>(emb_new, emb_new2, edge_nodes, edge_size,
                               node_degree, global_emb, qW, qb, acc);

    finalize_kernel<<<(N_NODES * OUT_DIM + 255) / 256, blk>>>(acc, node_degree, out);
}

// round 2
// speedup vs baseline: 1.1383x; 1.1383x over previous
#include <cuda_runtime.h>
#include <math.h>

#define N_NODES 30000
#define N_EDGES 60000
#define FEAT    256
#define HID     1024
#define OUT_DIM 256
#define RANK    64

// ---------------- scratch (static device globals; no runtime allocation) ----
__device__ float g_emb_new [(size_t)N_NODES * RANK];
__device__ float g_hid     [(size_t)N_NODES * HID];
__device__ float g_emb_new2[(size_t)N_NODES * OUT_DIM];
__device__ float g_acc     [(size_t)N_NODES * OUT_DIM];

// ================= 128x128x16 SGEMM, 8x8 per-thread register tile ==========
// C = act(A @ W[:K] + wrow + bias); A: MxK row-major, W: (K(+1))xN row-major.
#define BM 128
#define BN 128
#define BK 16

__global__ __launch_bounds__(256) void gemm128_kernel(
    const float* __restrict__ A, const float* __restrict__ W,
    const float* __restrict__ bias, const float* __restrict__ wrow,
    float* __restrict__ C, int M, int N, int K, int do_relu)
{
    __shared__ float As[BK][BM + 4];
    __shared__ float Bs[BK][BN];
    const int tid = threadIdx.x;
    const int tx  = tid & 15;           // 0..15 -> 8 output cols each
    const int ty  = tid >> 4;           // 0..15 -> 8 output rows each
    const int m0  = blockIdx.y * BM;
    const int n0  = blockIdx.x * BN;

    const int arow = tid >> 2;          // 0..63 (two passes of 64 rows)
    const int acol = (tid & 3) << 2;    // 0,4,8,12
    const int brow = tid >> 5;          // 0..7 (two passes of 8 rows)
    const int bcol = (tid & 31) << 2;   // 0..124

    float acc[8][8];
#pragma unroll
    for (int i = 0; i < 8; i++)
#pragma unroll
        for (int j = 0; j < 8; j++) acc[i][j] = 0.f;

    for (int k0 = 0; k0 < K; k0 += BK) {
#pragma unroll
        for (int p = 0; p < 2; p++) {
            const int r = arow + p * 64;
            float4 av = make_float4(0.f, 0.f, 0.f, 0.f);
            if (m0 + r < M)
                av = *(const float4*)(A + (size_t)(m0 + r) * K + k0 + acol);
            As[acol + 0][r] = av.x;
            As[acol + 1][r] = av.y;
            As[acol + 2][r] = av.z;
            As[acol + 3][r] = av.w;
        }
#pragma unroll
        for (int p = 0; p < 2; p++) {
            const int r = brow + p * 8;
            *(float4*)&Bs[r][bcol] =
                *(const float4*)(W + (size_t)(k0 + r) * N + n0 + bcol);
        }
        __syncthreads();
#pragma unroll
        for (int k = 0; k < BK; k++) {
            float a[8], b[8];
            *(float4*)&a[0] = *(const float4*)&As[k][ty * 8];
            *(float4*)&a[4] = *(const float4*)&As[k][ty * 8 + 4];
            *(float4*)&b[0] = *(const float4*)&Bs[k][tx * 8];
            *(float4*)&b[4] = *(const float4*)&Bs[k][tx * 8 + 4];
#pragma unroll
            for (int i = 0; i < 8; i++)
#pragma unroll
                for (int j = 0; j < 8; j++)
                    acc[i][j] = fmaf(a[i], b[j], acc[i][j]);
        }
        __syncthreads();
    }

    float bn[8];
#pragma unroll
    for (int j = 0; j < 8; j++) {
        const int n = n0 + tx * 8 + j;
        bn[j] = bias[n] + (wrow ? wrow[n] : 0.f);
    }
#pragma unroll
    for (int i = 0; i < 8; i++) {
        const int m = m0 + ty * 8 + i;
        if (m < M) {
            float v[8];
#pragma unroll
            for (int j = 0; j < 8; j++) {
                v[j] = acc[i][j] + bn[j];
                if (do_relu) v[j] = fmaxf(v[j], 0.f);
            }
            float* cp = C + (size_t)m * N + n0 + tx * 8;
            *(float4*)cp       = *(float4*)&v[0];
            *(float4*)(cp + 4) = *(float4*)&v[4];
        }
    }
}

// ---------------- 64x64 SGEMM (for N=64 output: pW) -------------------------
#define TM 64
#define TN 64
#define TK 16
#define SST 72

__global__ __launch_bounds__(256) void gemm64_kernel(
    const float* __restrict__ A, const float* __restrict__ W,
    const float* __restrict__ bias, const float* __restrict__ wrow,
    float* __restrict__ C, int M, int N, int K, int do_relu)
{
    __shared__ float As[TK][SST];
    __shared__ float Bs[TK][SST];
    const int tid = threadIdx.x;
    const int tx  = tid & 15;
    const int ty  = tid >> 4;
    const int m0  = blockIdx.y * TM;
    const int n0  = blockIdx.x * TN;

    const int arow = tid >> 2;
    const int acol = (tid & 3) << 2;
    const int brow = tid >> 4;
    const int bcol = (tid & 15) << 2;

    float acc[4][4] = {{0.f,0.f,0.f,0.f},{0.f,0.f,0.f,0.f},
                       {0.f,0.f,0.f,0.f},{0.f,0.f,0.f,0.f}};

    for (int k0 = 0; k0 < K; k0 += TK) {
        float4 av = make_float4(0.f, 0.f, 0.f, 0.f);
        if (m0 + arow < M)
            av = *(const float4*)(A + (size_t)(m0 + arow) * K + k0 + acol);
        As[acol + 0][arow] = av.x;
        As[acol + 1][arow] = av.y;
        As[acol + 2][arow] = av.z;
        As[acol + 3][arow] = av.w;
        *(float4*)&Bs[brow][bcol] =
            *(const float4*)(W + (size_t)(k0 + brow) * N + n0 + bcol);
        __syncthreads();
#pragma unroll
        for (int k = 0; k < TK; k++) {
            float4 a = *(const float4*)&As[k][ty << 2];
            float4 b = *(const float4*)&Bs[k][tx << 2];
            acc[0][0] = fmaf(a.x, b.x, acc[0][0]);
            acc[0][1] = fmaf(a.x, b.y, acc[0][1]);
            acc[0][2] = fmaf(a.x, b.z, acc[0][2]);
            acc[0][3] = fmaf(a.x, b.w, acc[0][3]);
            acc[1][0] = fmaf(a.y, b.x, acc[1][0]);
            acc[1][1] = fmaf(a.y, b.y, acc[1][1]);
            acc[1][2] = fmaf(a.y, b.z, acc[1][2]);
            acc[1][3] = fmaf(a.y, b.w, acc[1][3]);
            acc[2][0] = fmaf(a.z, b.x, acc[2][0]);
            acc[2][1] = fmaf(a.z, b.y, acc[2][1]);
            acc[2][2] = fmaf(a.z, b.z, acc[2][2]);
            acc[2][3] = fmaf(a.z, b.w, acc[2][3]);
            acc[3][0] = fmaf(a.w, b.x, acc[3][0]);
            acc[3][1] = fmaf(a.w, b.y, acc[3][1]);
            acc[3][2] = fmaf(a.w, b.z, acc[3][2]);
            acc[3][3] = fmaf(a.w, b.w, acc[3][3]);
        }
        __syncthreads();
    }

    float bn[4];
#pragma unroll
    for (int j = 0; j < 4; j++) {
        int n = n0 + (tx << 2) + j;
        bn[j] = bias[n] + (wrow ? wrow[n] : 0.f);
    }
#pragma unroll
    for (int i = 0; i < 4; i++) {
        int m = m0 + (ty << 2) + i;
        if (m < M) {
            float4 v;
            v.x = acc[i][0] + bn[0];
            v.y = acc[i][1] + bn[1];
            v.z = acc[i][2] + bn[2];
            v.w = acc[i][3] + bn[3];
            if (do_relu) {
                v.x = fmaxf(v.x, 0.f); v.y = fmaxf(v.y, 0.f);
                v.z = fmaxf(v.z, 0.f); v.w = fmaxf(v.w, 0.f);
            }
            *(float4*)(C + (size_t)m * N + n0 + (tx << 2)) = v;
        }
    }
}

// ---------------- edge kernel -----------------------------------------------
__global__ __launch_bounds__(256) void edge_kernel(
    const float* __restrict__ emb_new,
    const float* __restrict__ emb_new2,
    const int*   __restrict__ edge_nodes,
    const int*   __restrict__ edge_size,
    const int*   __restrict__ node_degree,
    const float* __restrict__ global_emb,
    const float* __restrict__ qW,
    const float* __restrict__ qb,
    float*       __restrict__ accum)
{
    __shared__ float s_t[4][RANK];
    __shared__ float s_h[4][RANK];
    __shared__ float sge[RANK];
    const int tid = threadIdx.x;
    const int s   = tid >> 6;     // slot 0..3
    const int j   = tid & 63;     // rank index

    float qw[RANK];
#pragma unroll
    for (int jj = 0; jj < RANK; jj++) qw[jj] = qW[jj * OUT_DIM + tid];
    const float qbc = qb[tid];
    if (tid < RANK) sge[tid] = global_emb[tid];
    __syncthreads();

    for (int e = blockIdx.x; e < N_EDGES; e += gridDim.x) {
        const int4 nd = ((const int4*)edge_nodes)[e];
        const int sz = edge_size[e];
        const int myn = (s == 0) ? nd.x : (s == 1) ? nd.y : (s == 2) ? nd.z : nd.w;

        // phase 1: t_{s,j} into smem (all 256 threads in parallel)
        float tval = 1.f;
        if (s < sz) {
            const float d  = (float)node_degree[myn];
            const float sc = (sz <= 3) ? cbrtf(d) : sqrtf(sqrtf(d));
            tval = sc * emb_new[(size_t)myn * RANK + j];
        }
        s_t[s][j] = tval;

        // r2 = relu(sum emb_new2[nodes]) for output col tid (gmem, indep of smem)
        float r2 = emb_new2[(size_t)nd.x * OUT_DIM + tid]
                 + emb_new2[(size_t)nd.y * OUT_DIM + tid];
        if (sz > 2) r2 += emb_new2[(size_t)nd.z * OUT_DIM + tid];
        if (sz > 3) r2 += emb_new2[(size_t)nd.w * OUT_DIM + tid];
        r2 = fmaxf(r2, 0.f);
        __syncthreads();

        // phase 2: h_{s,j} = tanh(prod_{r!=s} t_r * gf)
        if (s < sz) {
            const int   kk   = 4 - sz;
            const float ge   = sge[j];
            const float invf = (sz == 2) ? 1.f : (sz == 3) ? 0.5f : (1.f / 6.f);
            float p = invf * ((kk == 0) ? 1.f : (kk == 1) ? ge : ge * ge);
#pragma unroll
            for (int r = 0; r < 4; r++)
                if (r != s) p *= s_t[r][j];
            s_h[s][j] = tanhf(p);
        }
        __syncthreads();

        // phase 3: per-slot matvec h @ qW (qW col resident in regs) + atomics
        auto slot = [&](const float* hrow, int node) {
            const float4* h4 = (const float4*)hrow;
            float a = qbc;
#pragma unroll
            for (int jj = 0; jj < 16; jj++) {
                float4 hv = h4[jj];
                a = fmaf(hv.x, qw[4 * jj + 0], a);
                a = fmaf(hv.y, qw[4 * jj + 1], a);
                a = fmaf(hv.z, qw[4 * jj + 2], a);
                a = fmaf(hv.w, qw[4 * jj + 3], a);
            }
            atomicAdd(&accum[(size_t)node * OUT_DIM + tid], a + r2);
        };
        slot(s_h[0], nd.x);
        slot(s_h[1], nd.y);
        if (sz > 2) slot(s_h[2], nd.z);
        if (sz > 3) slot(s_h[3], nd.w);

        __syncthreads();   // protect smem reuse next edge
    }
}

// ---------------- helpers ----------------------------------------------------
__global__ void zero_kernel(float* __restrict__ p, int n)
{
    int i = blockIdx.x * blockDim.x + threadIdx.x;
    if (i < n) p[i] = 0.f;
}

__global__ void finalize_kernel(const float* __restrict__ accum,
                                const int*   __restrict__ node_degree,
                                float*       __restrict__ out)
{
    int idx = blockIdx.x * blockDim.x + threadIdx.x;
    if (idx < N_NODES * OUT_DIM) {
        int node = idx >> 8;   // OUT_DIM == 256
        float v = accum[idx] / (float)node_degree[node];
        out[idx] += fmaxf(v, 0.f);   // out already holds the relu residual
    }
}

// ---------------- launch -----------------------------------------------------
extern "C" void kernel_launch(void* const* d_in, const int* in_sizes, int n_in,
                              void* d_out, int out_size)
{
    (void)in_sizes; (void)n_in; (void)out_size;
    const float* embedding  = (const float*)d_in[0];
    const float* global_emb = (const float*)d_in[1];
    const float* pW   = (const float*)d_in[2];
    const float* pb   = (const float*)d_in[3];
    const float* qW   = (const float*)d_in[4];
    const float* qb   = (const float*)d_in[5];
    const float* p2W1 = (const float*)d_in[6];
    const float* p2b1 = (const float*)d_in[7];
    const float* p2W2 = (const float*)d_in[8];
    const float* p2b2 = (const float*)d_in[9];
    const float* aW   = (const float*)d_in[10];
    const float* ab   = (const float*)d_in[11];
    const int* edge_nodes  = (const int*)d_in[12];
    // d_in[13] = edge_mask (bool) — unused: mask[s] == (s < edge_size)
    const int* edge_size   = (const int*)d_in[14];
    const int* node_degree = (const int*)d_in[15];
    float* out = (float*)d_out;

    float *emb_new, *hid, *emb_new2, *acc;
    cudaGetSymbolAddress((void**)&emb_new,  g_emb_new);
    cudaGetSymbolAddress((void**)&hid,      g_hid);
    cudaGetSymbolAddress((void**)&emb_new2, g_emb_new2);
    cudaGetSymbolAddress((void**)&acc,      g_acc);

    dim3 blk(256);
    const int mby64  = (N_NODES + TM - 1) / TM;   // 469
    const int mby128 = (N_NODES + BM - 1) / BM;   // 235

    // emb_new = embedding @ pW[:256] + pW[256] + pb   (N=64 -> 64-tile kernel)
    gemm64_kernel<<<dim3(RANK / TN, mby64), blk>>>(
        embedding, pW, pb, pW + (size_t)FEAT * RANK,
        emb_new, N_NODES, RANK, FEAT, 0);
    // hid = relu(embedding @ p2W1[:256] + p2W1[256] + p2b1)
    gemm128_kernel<<<dim3(HID / BN, mby128), blk>>>(
        embedding, p2W1, p2b1, p2W1 + (size_t)FEAT * HID,
        hid, N_NODES, HID, FEAT, 1);
    // emb_new2 = hid @ p2W2 + p2b2
    gemm128_kernel<<<dim3(OUT_DIM / BN, mby128), blk>>>(
        hid, p2W2, p2b2, nullptr,
        emb_new2, N_NODES, OUT_DIM, HID, 0);
    // residual = relu(embedding @ aW[:256] + aW[256] + ab) -> d_out
    gemm128_kernel<<<dim3(OUT_DIM / BN, mby128), blk>>>(
        embedding, aW, ab, aW + (size_t)FEAT * OUT_DIM,
        out, N_NODES, OUT_DIM, FEAT, 1);

    zero_kernel<<<(N_NODES * OUT_DIM + 255) / 256, blk>>>(acc, N_NODES * OUT_DIM);

    edge_kernel<<<1480, blk>>>(emb_new, emb_new2, edge_nodes, edge_size,
                               node_degree, global_emb, qW, qb, acc);

    finalize_kernel<<<(N_NODES * OUT_DIM + 255) / 256, blk>>>(acc, node_degree, out);
}